// round 6
// baseline (speedup 1.0000x reference)
#include <cuda_runtime.h>
#include <cuda_bf16.h>
#include <cstdint>

// ---------------- problem constants ----------------
#define BATCH   8
#define SEQ     4096
#define DMODEL  1024
#define MTOT    (BATCH * SEQ)      // 32768
#define KTOT    DMODEL             // 1024
#define NTOT    (2 * DMODEL)       // 2048 fused (decay | input)

// ---------------- GEMM tiling ----------------
#define M_TILE   128
#define N_TILE   128
#define K_CHUNK  32
#define N_CHUNKS (KTOT / K_CHUNK)   // 32
#define GTHREADS 256
#define NSTAGE   2

// smem: padded pitch 40 bf16 (80 B) -> conflict-free ldmatrix
#define PITCH 40
#define TILE_BYTES (128 * PITCH * 2)      // 10240
#define OFF_A_HI 0
#define OFF_A_LO (1 * TILE_BYTES)
#define OFF_B_HI (2 * TILE_BYTES)
#define OFF_B_LO (3 * TILE_BYTES)
#define STAGE_BYTES (4 * TILE_BYTES)      // 40960
#define SMEM_TOTAL  (NSTAGE * STAGE_BYTES) // 81920 -> 2 CTAs/SM = 160KB

// ---------------- scan segmentation ----------------
#define NSEG   16
#define SEGLEN (SEQ / NSEG)         // 256

// ---------------- device scratch ----------------
__device__ __nv_bfloat16 X_hi[(size_t)MTOT * KTOT];
__device__ __nv_bfloat16 X_lo[(size_t)MTOT * KTOT];
__device__ __nv_bfloat16 Wf_hi[(size_t)NTOT * KTOT];
__device__ __nv_bfloat16 Wf_lo[(size_t)NTOT * KTOT];
__device__ float g_decays[(size_t)MTOT * DMODEL];
__device__ float g_inj[(size_t)MTOT * DMODEL];
__device__ float g_segA[BATCH * NSEG * DMODEL];
__device__ float g_segB[BATCH * NSEG * DMODEL];
__device__ float g_segInit[BATCH * NSEG * DMODEL];

// ---------------- PTX helpers ----------------
__device__ __forceinline__ uint32_t s2u(const void* p) {
    return (uint32_t)__cvta_generic_to_shared(p);
}

#define CPA16(s, g) asm volatile("cp.async.cg.shared.global [%0], [%1], 16;" :: "r"(s), "l"(g) : "memory")
#define CPA_COMMIT() asm volatile("cp.async.commit_group;" ::: "memory")
#define CPA_WAIT1()  asm volatile("cp.async.wait_group 1;" ::: "memory")
#define CPA_WAIT0()  asm volatile("cp.async.wait_group 0;" ::: "memory")

__device__ __forceinline__ void ldsm_x4(uint32_t addr, uint32_t& r0, uint32_t& r1,
                                        uint32_t& r2, uint32_t& r3) {
    asm volatile("ldmatrix.sync.aligned.m8n8.x4.shared.b16 {%0,%1,%2,%3}, [%4];"
                 : "=r"(r0), "=r"(r1), "=r"(r2), "=r"(r3) : "r"(addr));
}

__device__ __forceinline__ void mma16816(float* c, const uint32_t* a,
                                         uint32_t b0, uint32_t b1) {
    asm volatile(
        "mma.sync.aligned.m16n8k16.row.col.f32.bf16.bf16.f32 "
        "{%0,%1,%2,%3}, {%4,%5,%6,%7}, {%8,%9}, {%0,%1,%2,%3};"
        : "+f"(c[0]), "+f"(c[1]), "+f"(c[2]), "+f"(c[3])
        : "r"(a[0]), "r"(a[1]), "r"(a[2]), "r"(a[3]), "r"(b0), "r"(b1));
}

// ---------------- fp32 -> bf16 hi/lo split ----------------
__device__ __forceinline__ void split_bf(float x, unsigned short& h, unsigned short& l) {
    __nv_bfloat16 hb = __float2bfloat16_rn(x);
    float hf = __bfloat162float(hb);
    __nv_bfloat16 lb = __float2bfloat16_rn(x - hf);
    h = __bfloat16_as_ushort(hb);
    l = __bfloat16_as_ushort(lb);
}

__global__ __launch_bounds__(256)
void convert_x_kernel(const float* __restrict__ x) {
    size_t i = (size_t)blockIdx.x * 256 + threadIdx.x;      // float4 index
    float4 v = reinterpret_cast<const float4*>(x)[i];
    unsigned short h0, h1, h2, h3, l0, l1, l2, l3;
    split_bf(v.x, h0, l0); split_bf(v.y, h1, l1);
    split_bf(v.z, h2, l2); split_bf(v.w, h3, l3);
    uint2 uh, ul;
    uh.x = (uint32_t)h0 | ((uint32_t)h1 << 16);
    uh.y = (uint32_t)h2 | ((uint32_t)h3 << 16);
    ul.x = (uint32_t)l0 | ((uint32_t)l1 << 16);
    ul.y = (uint32_t)l2 | ((uint32_t)l3 << 16);
    reinterpret_cast<uint2*>(X_hi)[i] = uh;
    reinterpret_cast<uint2*>(X_lo)[i] = ul;
}

__global__ __launch_bounds__(256)
void convert_w_kernel(const float* __restrict__ Wd, const float* __restrict__ Wi) {
    size_t i = (size_t)blockIdx.x * 256 + threadIdx.x;      // float4 index, 524288
    int row = (int)(i >> 8);
    int c4  = (int)(i & 255);
    const float* src = (row < DMODEL) ? (Wd + (size_t)row * KTOT)
                                      : (Wi + (size_t)(row - DMODEL) * KTOT);
    float4 v = reinterpret_cast<const float4*>(src)[c4];
    unsigned short h0, h1, h2, h3, l0, l1, l2, l3;
    split_bf(v.x, h0, l0); split_bf(v.y, h1, l1);
    split_bf(v.z, h2, l2); split_bf(v.w, h3, l3);
    uint2 uh, ul;
    uh.x = (uint32_t)h0 | ((uint32_t)h1 << 16);
    uh.y = (uint32_t)h2 | ((uint32_t)h3 << 16);
    ul.x = (uint32_t)l0 | ((uint32_t)l1 << 16);
    ul.y = (uint32_t)l2 | ((uint32_t)l3 << 16);
    reinterpret_cast<uint2*>(Wf_hi)[i] = uh;
    reinterpret_cast<uint2*>(Wf_lo)[i] = ul;
}

// ---------------- GEMM: load one K-chunk into a stage ----------------
// 256 threads: A = 128 rows x 4 16B-chunks = 512 transfers -> 2 iters; same for B.
__device__ __forceinline__ void load_chunk(uint32_t smem_u, int c, int st,
                                           int m0, int n0, int tid) {
    const int k0 = c * K_CHUNK;
    const uint32_t base = smem_u + st * STAGE_BYTES;
#pragma unroll
    for (int it = 0; it < 2; ++it) {
        int idx = it * 256 + tid;
        int row = idx >> 2;
        int kk  = (idx & 3) * 8;
        uint32_t so = (uint32_t)(row * PITCH + kk) * 2;
        size_t gA = (size_t)(m0 + row) * KTOT + k0 + kk;
        size_t gB = (size_t)(n0 + row) * KTOT + k0 + kk;
        CPA16(base + OFF_A_HI + so, X_hi + gA);
        CPA16(base + OFF_A_LO + so, X_lo + gA);
        CPA16(base + OFF_B_HI + so, Wf_hi + gB);
        CPA16(base + OFF_B_LO + so, Wf_lo + gB);
    }
}

// ---------------- GEMM + gate epilogue (mma.sync bf16, 3-pass split) ----------------
// 8 warps in 4(m) x 2(n) layout; warp tile 32x64; 2 CTAs/SM.
__global__ __launch_bounds__(GTHREADS, 2)
void gemm_tc_kernel(const float* __restrict__ bd, const float* __restrict__ bi) {
    extern __shared__ char smem[];
    const uint32_t smem_u = s2u(smem);
    const int tid = threadIdx.x;
    const int wid = tid >> 5;
    const int lane = tid & 31;

    const int n0 = blockIdx.x * N_TILE;        // 0..1920
    const int m0 = blockIdx.y * M_TILE;
    const bool is_decay = (n0 < DMODEL);
    const int colbase = is_decay ? n0 : (n0 - DMODEL);
    const float* bv = is_decay ? bd : bi;

    const int warp_m = (wid & 3) * 32;         // 4 warps along M
    const int warp_n = (wid >> 2) * 64;        // 2 warps along N

    float acc[2][8][4];
#pragma unroll
    for (int mt = 0; mt < 2; ++mt)
#pragma unroll
        for (int nt = 0; nt < 8; ++nt)
#pragma unroll
            for (int q = 0; q < 4; ++q) acc[mt][nt][q] = 0.0f;

    // ldmatrix lane addressing
    const int a_r = lane & 15;
    const int a_c = (lane >> 4) * 8;
    const int b_quad = lane >> 3;
    const int b_r = lane & 7;
    const int b_row_off = ((b_quad >> 1) * 8) + b_r;
    const int b_k_off = (b_quad & 1) * 8;

    // prologue
    load_chunk(smem_u, 0, 0, m0, n0, tid); CPA_COMMIT();
    load_chunk(smem_u, 1, 1, m0, n0, tid); CPA_COMMIT();

    for (int c = 0; c < N_CHUNKS; ++c) {
        const int st = c & 1;
        if (c == N_CHUNKS - 1) { CPA_WAIT0(); } else { CPA_WAIT1(); }
        __syncthreads();

        const uint32_t base = smem_u + st * STAGE_BYTES;
#pragma unroll
        for (int kh = 0; kh < 2; ++kh) {
            const int kc = kh * 16;
            uint32_t ah[2][4], al[2][4];
#pragma unroll
            for (int mt = 0; mt < 2; ++mt) {
                uint32_t off = (uint32_t)((warp_m + mt * 16 + a_r) * PITCH + kc + a_c) * 2;
                ldsm_x4(base + OFF_A_HI + off, ah[mt][0], ah[mt][1], ah[mt][2], ah[mt][3]);
                ldsm_x4(base + OFF_A_LO + off, al[mt][0], al[mt][1], al[mt][2], al[mt][3]);
            }
#pragma unroll
            for (int ng = 0; ng < 4; ++ng) {   // 4 n16 groups (warp_n = 64)
                uint32_t off = (uint32_t)((warp_n + ng * 16 + b_row_off) * PITCH + kc + b_k_off) * 2;
                // B-hi: used by both A-hi and A-lo passes while live
                {
                    uint32_t b0, b1, b2, b3;
                    ldsm_x4(base + OFF_B_HI + off, b0, b1, b2, b3);
#pragma unroll
                    for (int mt = 0; mt < 2; ++mt) {
                        mma16816(acc[mt][2 * ng + 0], ah[mt], b0, b1);
                        mma16816(acc[mt][2 * ng + 1], ah[mt], b2, b3);
                        mma16816(acc[mt][2 * ng + 0], al[mt], b0, b1);
                        mma16816(acc[mt][2 * ng + 1], al[mt], b2, b3);
                    }
                }
                // B-lo: A-hi pass only
                {
                    uint32_t b0, b1, b2, b3;
                    ldsm_x4(base + OFF_B_LO + off, b0, b1, b2, b3);
#pragma unroll
                    for (int mt = 0; mt < 2; ++mt) {
                        mma16816(acc[mt][2 * ng + 0], ah[mt], b0, b1);
                        mma16816(acc[mt][2 * ng + 1], ah[mt], b2, b3);
                    }
                }
            }
        }
        __syncthreads();
        if (c + 2 < N_CHUNKS) {
            load_chunk(smem_u, c + 2, st, m0, n0, tid);
            CPA_COMMIT();
        }
    }

    // ---- epilogue: bias (+sigmoid), direct float2 stores ----
    float* dst = is_decay ? g_decays : g_inj;
#pragma unroll
    for (int mt = 0; mt < 2; ++mt) {
        int row0 = m0 + warp_m + mt * 16 + (lane >> 2);
#pragma unroll
        for (int nt = 0; nt < 8; ++nt) {
            int gcol = colbase + warp_n + nt * 8 + (lane & 3) * 2;
            float2 bias2 = *reinterpret_cast<const float2*>(bv + gcol);
            float v0 = acc[mt][nt][0] + bias2.x;
            float v1 = acc[mt][nt][1] + bias2.y;
            float v2 = acc[mt][nt][2] + bias2.x;
            float v3 = acc[mt][nt][3] + bias2.y;
            if (is_decay) {
                v0 = __fdividef(1.0f, 1.0f + __expf(-v0));
                v1 = __fdividef(1.0f, 1.0f + __expf(-v1));
                v2 = __fdividef(1.0f, 1.0f + __expf(-v2));
                v3 = __fdividef(1.0f, 1.0f + __expf(-v3));
            }
            *reinterpret_cast<float2*>(dst + (size_t)row0 * DMODEL + gcol) =
                make_float2(v0, v1);
            *reinterpret_cast<float2*>(dst + (size_t)(row0 + 8) * DMODEL + gcol) =
                make_float2(v2, v3);
        }
    }
}

// ---------------- segmented scan ----------------
__global__ __launch_bounds__(256)
void scan_pass1() {
    const int g = blockIdx.x * 256 + threadIdx.x;      // 0..131071
    const int e = g & (DMODEL - 1);
    const int bs = g >> 10;
    const int seg = bs & (NSEG - 1);
    const int b = bs >> 4;
    size_t p = ((size_t)b * SEQ + (size_t)seg * SEGLEN) * DMODEL + e;

    float s = 0.0f, A = 1.0f;
    for (int t = 0; t < SEGLEN; t += 8) {
        float d[8], v[8];
#pragma unroll
        for (int j = 0; j < 8; ++j) {
            d[j] = g_decays[p + (size_t)j * DMODEL];
            v[j] = g_inj[p + (size_t)j * DMODEL];
        }
#pragma unroll
        for (int j = 0; j < 8; ++j) {
            s = fmaf(d[j], s, v[j]);
            A *= d[j];
        }
        p += (size_t)8 * DMODEL;
    }
    g_segA[g] = A;
    g_segB[g] = s;
}

__global__ __launch_bounds__(256)
void scan_pass2() {
    const int g = blockIdx.x * 256 + threadIdx.x;      // 0..8191
    const int e = g & (DMODEL - 1);
    const int b = g >> 10;
    float s = 0.0f;
#pragma unroll
    for (int seg = 0; seg < NSEG; ++seg) {
        int idx = ((b * NSEG + seg) << 10) | e;
        g_segInit[idx] = s;
        s = fmaf(g_segA[idx], s, g_segB[idx]);
    }
}

__global__ __launch_bounds__(256)
void scan_pass3(float* __restrict__ out) {
    const int g = blockIdx.x * 256 + threadIdx.x;
    const int e = g & (DMODEL - 1);
    const int bs = g >> 10;
    const int seg = bs & (NSEG - 1);
    const int b = bs >> 4;
    size_t p = ((size_t)b * SEQ + (size_t)seg * SEGLEN) * DMODEL + e;

    float s = g_segInit[g];
    for (int t = 0; t < SEGLEN; t += 8) {
        float d[8], v[8];
#pragma unroll
        for (int j = 0; j < 8; ++j) {
            d[j] = g_decays[p + (size_t)j * DMODEL];
            v[j] = g_inj[p + (size_t)j * DMODEL];
        }
#pragma unroll
        for (int j = 0; j < 8; ++j) {
            s = fmaf(d[j], s, v[j]);
            out[p + (size_t)j * DMODEL] = s;
        }
        p += (size_t)8 * DMODEL;
    }
}

// ---------------- launch ----------------
extern "C" void kernel_launch(void* const* d_in, const int* in_sizes, int n_in,
                              void* d_out, int out_size) {
    const float* x_seq   = (const float*)d_in[0];
    const float* W_decay = (const float*)d_in[1];
    const float* b_decay = (const float*)d_in[2];
    const float* W_input = (const float*)d_in[3];
    const float* b_input = (const float*)d_in[4];
    float* out = (float*)d_out;

    static bool attr_set = false;
    if (!attr_set) {
        cudaFuncSetAttribute(gemm_tc_kernel,
                             cudaFuncAttributeMaxDynamicSharedMemorySize, SMEM_TOTAL);
        attr_set = true;
    }

    convert_x_kernel<<<(MTOT * KTOT / 4) / 256, 256>>>(x_seq);
    convert_w_kernel<<<(NTOT * KTOT / 4) / 256, 256>>>(W_decay, W_input);

    dim3 grid(NTOT / N_TILE, MTOT / M_TILE);   // (16, 256): n fastest -> A reuse in L2
    gemm_tc_kernel<<<grid, GTHREADS, SMEM_TOTAL>>>(b_decay, b_input);

    scan_pass1<<<(BATCH * NSEG * DMODEL) / 256, 256>>>();
    scan_pass2<<<(BATCH * DMODEL) / 256, 256>>>();
    scan_pass3<<<(BATCH * NSEG * DMODEL) / 256, 256>>>(out);
}